// round 1
// baseline (speedup 1.0000x reference)
#include <cuda_runtime.h>
#include <cstdint>

// ---------------------------------------------------------------------------
// Problem constants
// ---------------------------------------------------------------------------
#define BATCH 4
#define CH    768
#define TLEN  1000
#define SPAT  64          // 8*8
#define HEADS 12
#define HDIM  64          // CH / HEADS
#define WSZ   16
#define NWIN  63          // ceil(1000/16) -> 1008/16
#define NTOK  (BATCH*TLEN)       // 4000
#define MLPC  (4*CH)             // 3072

// ---------------------------------------------------------------------------
// Scratch (device globals; allocation-free)
// ---------------------------------------------------------------------------
__device__ float g_s  [NTOK*CH];
__device__ float g_sn [NTOK*CH];
__device__ float g_qkv[NTOK*3*CH];
__device__ float g_att[NTOK*CH];
__device__ float g_y0 [NTOK*CH];
__device__ float g_mlp[NTOK*MLPC];
__device__ float g_o  [NTOK*CH];

// ---------------------------------------------------------------------------
// Helpers
// ---------------------------------------------------------------------------
__device__ __forceinline__ float to_tf32(float x) {
    uint32_t u;
    asm("cvt.rna.tf32.f32 %0, %1;" : "=r"(u) : "f"(x));
    return __uint_as_float(u);
}

__device__ __forceinline__ void mma_tf32(float* c, const uint32_t* a, const uint32_t* b) {
    asm volatile(
        "mma.sync.aligned.m16n8k8.row.col.f32.tf32.tf32.f32 "
        "{%0,%1,%2,%3},{%4,%5,%6,%7},{%8,%9},{%0,%1,%2,%3};"
        : "+f"(c[0]), "+f"(c[1]), "+f"(c[2]), "+f"(c[3])
        : "r"(a[0]), "r"(a[1]), "r"(a[2]), "r"(a[3]), "r"(b[0]), "r"(b[1]));
}

// ---------------------------------------------------------------------------
// K1: spatial mean.  x (B,C,T,8,8) -> s[(b*T+t)*C + c] = mean over 64 spatial
// One 16-thread group per (b,c,t) row of 64 contiguous floats.
// ---------------------------------------------------------------------------
__global__ void spatial_mean_kernel(const float* __restrict__ x, float* __restrict__ s) {
    unsigned idx = blockIdx.x * 256u + threadIdx.x;
    unsigned row = idx >> 4;               // (b,c,t) index
    unsigned l16 = idx & 15u;
    if (row >= (unsigned)(BATCH*CH*TLEN)) return;
    float4 v = reinterpret_cast<const float4*>(x)[row * 16u + l16];
    float sum = v.x + v.y + v.z + v.w;
    sum += __shfl_xor_sync(0xffffffffu, sum, 1);
    sum += __shfl_xor_sync(0xffffffffu, sum, 2);
    sum += __shfl_xor_sync(0xffffffffu, sum, 4);
    sum += __shfl_xor_sync(0xffffffffu, sum, 8);
    if (l16 == 0) {
        unsigned t  = row % TLEN;
        unsigned bc = row / TLEN;
        unsigned c  = bc % CH;
        unsigned b  = bc / CH;
        s[(b*TLEN + t)*CH + c] = sum * (1.0f/64.0f);
    }
}

// ---------------------------------------------------------------------------
// K2: LayerNorm over C=768 per token
// ---------------------------------------------------------------------------
__global__ void ln_kernel(const float* __restrict__ s, const float* __restrict__ gg,
                          const float* __restrict__ bb, float* __restrict__ sn) {
    __shared__ float red[2][8];
    int tok = blockIdx.x;
    int tid = threadIdx.x;                 // 256
    const float* row = s + (size_t)tok * CH;
    float v0 = row[tid], v1 = row[tid+256], v2 = row[tid+512];
    float sum = v0+v1+v2;
    float sq  = v0*v0 + v1*v1 + v2*v2;
    #pragma unroll
    for (int m = 16; m; m >>= 1) {
        sum += __shfl_xor_sync(0xffffffffu, sum, m);
        sq  += __shfl_xor_sync(0xffffffffu, sq,  m);
    }
    if ((tid & 31) == 0) { red[0][tid>>5] = sum; red[1][tid>>5] = sq; }
    __syncthreads();
    if (tid < 32) {
        float a  = (tid < 8) ? red[0][tid] : 0.f;
        float b2 = (tid < 8) ? red[1][tid] : 0.f;
        #pragma unroll
        for (int m = 4; m; m >>= 1) {
            a  += __shfl_xor_sync(0xffffffffu, a,  m);
            b2 += __shfl_xor_sync(0xffffffffu, b2, m);
        }
        if (tid == 0) { red[0][0] = a; red[1][0] = b2; }
    }
    __syncthreads();
    float mean = red[0][0] * (1.0f/768.0f);
    float var  = red[1][0] * (1.0f/768.0f) - mean*mean;
    float rstd = rsqrtf(var + 1e-5f);
    float* orow = sn + (size_t)tok * CH;
    orow[tid    ] = (v0-mean)*rstd*gg[tid    ] + bb[tid    ];
    orow[tid+256] = (v1-mean)*rstd*gg[tid+256] + bb[tid+256];
    orow[tid+512] = (v2-mean)*rstd*gg[tid+512] + bb[tid+512];
}

// ---------------------------------------------------------------------------
// GEMM: C = A(MxK) @ B(KxN) + bias, tf32 mma.sync m16n8k8.
// Block tile 128x128x32, 8 warps (2x4), warp tile 64x32.
// EPI: 0 = bias, 1 = bias + exact GELU, 2 = bias + residual add
// N and K are multiples of 128/32; M (=4000) is guarded.
// ---------------------------------------------------------------------------
template<int EPI>
__global__ __launch_bounds__(256, 2)
void gemm_tf32(const float* __restrict__ A, const float* __restrict__ B,
               const float* __restrict__ bias, const float* __restrict__ Res,
               float* __restrict__ C, int M, int N, int K)
{
    __shared__ float As[128][36];
    __shared__ float Bs[32][132];
    int tid  = threadIdx.x;
    int lane = tid & 31, warp = tid >> 5;
    int wm = warp >> 2, wn = warp & 3;           // 2 x 4 warps
    int bm = blockIdx.y * 128, bn = blockIdx.x * 128;
    int g  = lane >> 2, tg = lane & 3;

    float acc[4][4][4];
    #pragma unroll
    for (int i = 0; i < 4; i++)
        #pragma unroll
        for (int j = 0; j < 4; j++)
            #pragma unroll
            for (int r = 0; r < 4; r++) acc[i][j][r] = 0.f;

    for (int k0 = 0; k0 < K; k0 += 32) {
        // A tile 128x32
        #pragma unroll
        for (int j = 0; j < 4; j++) {
            int idx = j*256 + tid;
            int r = idx >> 3, kc = (idx & 7) << 2;
            float4 v = make_float4(0.f,0.f,0.f,0.f);
            if (bm + r < M)
                v = *reinterpret_cast<const float4*>(A + (size_t)(bm+r)*K + k0 + kc);
            float4 w = make_float4(to_tf32(v.x), to_tf32(v.y), to_tf32(v.z), to_tf32(v.w));
            *reinterpret_cast<float4*>(&As[r][kc]) = w;
        }
        // B tile 32x128
        #pragma unroll
        for (int j = 0; j < 4; j++) {
            int idx = j*256 + tid;
            int r = idx >> 5, nc = (idx & 31) << 2;
            float4 v = *reinterpret_cast<const float4*>(B + (size_t)(k0+r)*N + bn + nc);
            float4 w = make_float4(to_tf32(v.x), to_tf32(v.y), to_tf32(v.z), to_tf32(v.w));
            *reinterpret_cast<float4*>(&Bs[r][nc]) = w;
        }
        __syncthreads();
        #pragma unroll
        for (int kk = 0; kk < 4; kk++) {
            int k = kk * 8;
            uint32_t af[4][4], bf[4][2];
            #pragma unroll
            for (int mi = 0; mi < 4; mi++) {
                int r = wm*64 + mi*16 + g;
                af[mi][0] = __float_as_uint(As[r  ][k+tg  ]);
                af[mi][1] = __float_as_uint(As[r+8][k+tg  ]);
                af[mi][2] = __float_as_uint(As[r  ][k+tg+4]);
                af[mi][3] = __float_as_uint(As[r+8][k+tg+4]);
            }
            #pragma unroll
            for (int ni = 0; ni < 4; ni++) {
                int cc = wn*32 + ni*8 + g;
                bf[ni][0] = __float_as_uint(Bs[k+tg  ][cc]);
                bf[ni][1] = __float_as_uint(Bs[k+4+tg][cc]);
            }
            #pragma unroll
            for (int mi = 0; mi < 4; mi++)
                #pragma unroll
                for (int ni = 0; ni < 4; ni++)
                    mma_tf32(acc[mi][ni], af[mi], bf[ni]);
        }
        __syncthreads();
    }

    // epilogue
    #pragma unroll
    for (int mi = 0; mi < 4; mi++) {
        #pragma unroll
        for (int ni = 0; ni < 4; ni++) {
            int r0 = bm + wm*64 + mi*16 + g;
            int c0 = bn + wn*32 + ni*8 + tg*2;
            #pragma unroll
            for (int reg = 0; reg < 4; reg++) {
                int r  = r0 + ((reg >= 2) ? 8 : 0);
                int cc = c0 + (reg & 1);
                if (r < M) {
                    float v = acc[mi][ni][reg] + bias[cc];
                    if (EPI == 1) v = v * normcdff(v);           // exact GELU
                    if (EPI == 2) v += Res[(size_t)r*N + cc];    // residual
                    C[(size_t)r*N + cc] = v;
                }
            }
        }
    }
}

// ---------------------------------------------------------------------------
// K4: windowed cosine attention. One block per (window, head, batch).
// Zero-padded K rows contribute logit 0 (matching jnp.pad semantics), V rows 0.
// ---------------------------------------------------------------------------
__global__ void attn_kernel(const float* __restrict__ qkv, const float* __restrict__ tau,
                            float* __restrict__ att) {
    __shared__ float qs[16][68], ks[16][68], vs[16][68];
    __shared__ float rq[16], rk[16];
    __shared__ float at[16][17];
    __shared__ float tauv;

    int n = blockIdx.x, hh = blockIdx.y, b = blockIdx.z;
    int tid = threadIdx.x;                  // 256

    // load q,k,v tiles (16 rows x 64), one float4 per thread per tensor
    {
        int r  = tid >> 4;
        int c4 = (tid & 15) << 2;
        int t  = n*WSZ + r;
        float4 q4 = make_float4(0.f,0.f,0.f,0.f), k4 = q4, v4 = q4;
        if (t < TLEN) {
            size_t base = (size_t)(b*TLEN + t) * (3*CH) + hh*HDIM + c4;
            q4 = *reinterpret_cast<const float4*>(qkv + base);
            k4 = *reinterpret_cast<const float4*>(qkv + base + CH);
            v4 = *reinterpret_cast<const float4*>(qkv + base + 2*CH);
        }
        *reinterpret_cast<float4*>(&qs[r][c4]) = q4;
        *reinterpret_cast<float4*>(&ks[r][c4]) = k4;
        *reinterpret_cast<float4*>(&vs[r][c4]) = v4;
        if (tid == 0) tauv = tau[hh] + 1e-6f;
    }
    __syncthreads();

    // row inverse norms for q and k
    if (tid < 32) {
        const float* p = (tid < 16) ? &qs[tid][0] : &ks[tid-16][0];
        float ssum = 0.f;
        #pragma unroll
        for (int i = 0; i < 64; i++) ssum += p[i]*p[i];
        float inv = 1.0f / fmaxf(sqrtf(ssum), 1e-12f);
        if (tid < 16) rq[tid] = inv; else rk[tid-16] = inv;
    }
    __syncthreads();

    // logits + softmax: thread (w, s2), 16 lanes per row, lane-aligned
    int w  = tid >> 4;
    int s2 = tid & 15;
    float dot = 0.f;
    #pragma unroll
    for (int i = 0; i < 64; i++) dot += qs[w][i] * ks[s2][i];
    float logit = dot * rq[w] * rk[s2] / tauv;

    float mx = logit;
    #pragma unroll
    for (int m = 8; m; m >>= 1) mx = fmaxf(mx, __shfl_xor_sync(0xffffffffu, mx, m));
    float e = expf(logit - mx);
    float ssum = e;
    #pragma unroll
    for (int m = 8; m; m >>= 1) ssum += __shfl_xor_sync(0xffffffffu, ssum, m);
    at[w][s2] = e / ssum;
    __syncthreads();

    // out = attn @ v : thread (w, 4 cols)
    int c0 = (tid & 15) << 2;
    float o0=0.f, o1=0.f, o2=0.f, o3=0.f;
    #pragma unroll
    for (int ss = 0; ss < 16; ss++) {
        float a = at[w][ss];
        o0 += a * vs[ss][c0+0];
        o1 += a * vs[ss][c0+1];
        o2 += a * vs[ss][c0+2];
        o3 += a * vs[ss][c0+3];
    }
    int t = n*WSZ + w;
    if (t < TLEN) {
        float4 o4 = make_float4(o0,o1,o2,o3);
        *reinterpret_cast<float4*>(att + (size_t)(b*TLEN + t)*CH + hh*HDIM + c0) = o4;
    }
}

// ---------------------------------------------------------------------------
// K8: y = x + o*0.5 broadcast over the 64 spatial positions
// ---------------------------------------------------------------------------
__global__ void final_kernel(const float* __restrict__ x, const float* __restrict__ o,
                             float* __restrict__ y) {
    unsigned i4 = blockIdx.x * 256u + threadIdx.x;    // over 49,152,000 float4
    if (i4 >= (unsigned)(BATCH*CH*TLEN*16)) return;
    unsigned row = i4 >> 4;              // (b,c,t)
    unsigned t  = row % TLEN;
    unsigned bc = row / TLEN;
    unsigned c  = bc % CH;
    unsigned b  = bc / CH;
    float val = __ldg(o + (size_t)(b*TLEN + t)*CH + c) * 0.5f;
    float4 xv = reinterpret_cast<const float4*>(x)[i4];
    xv.x += val; xv.y += val; xv.z += val; xv.w += val;
    reinterpret_cast<float4*>(y)[i4] = xv;
}

// ---------------------------------------------------------------------------
// Launch
// ---------------------------------------------------------------------------
extern "C" void kernel_launch(void* const* d_in, const int* in_sizes, int n_in,
                              void* d_out, int out_size) {
    const float* x      = (const float*)d_in[0];
    const float* ln_g   = (const float*)d_in[1];
    const float* ln_b   = (const float*)d_in[2];
    const float* tau    = (const float*)d_in[3];
    const float* w_qkv  = (const float*)d_in[4];
    const float* b_qkv  = (const float*)d_in[5];
    const float* w_proj = (const float*)d_in[6];
    const float* b_proj = (const float*)d_in[7];
    const float* w_mlp1 = (const float*)d_in[8];
    const float* b_mlp1 = (const float*)d_in[9];
    const float* w_mlp2 = (const float*)d_in[10];
    const float* b_mlp2 = (const float*)d_in[11];
    float* y = (float*)d_out;

    float *s, *sn, *qkv, *att, *y0, *mlp, *o;
    cudaGetSymbolAddress((void**)&s,   g_s);
    cudaGetSymbolAddress((void**)&sn,  g_sn);
    cudaGetSymbolAddress((void**)&qkv, g_qkv);
    cudaGetSymbolAddress((void**)&att, g_att);
    cudaGetSymbolAddress((void**)&y0,  g_y0);
    cudaGetSymbolAddress((void**)&mlp, g_mlp);
    cudaGetSymbolAddress((void**)&o,   g_o);

    const int elem_rows = BATCH*CH*TLEN;                 // 3,072,000
    spatial_mean_kernel<<<(elem_rows*16 + 255)/256, 256>>>(x, s);
    ln_kernel<<<NTOK, 256>>>(s, ln_g, ln_b, sn);

    // qkv: 4000 x 2304 = sn @ w_qkv
    gemm_tf32<0><<<dim3(3*CH/128, 32), 256>>>(sn, w_qkv, b_qkv, nullptr, qkv, NTOK, 3*CH, CH);

    attn_kernel<<<dim3(NWIN, HEADS, BATCH), 256>>>(qkv, tau, att);

    // proj: 4000 x 768
    gemm_tf32<0><<<dim3(CH/128, 32), 256>>>(att, w_proj, b_proj, nullptr, y0, NTOK, CH, CH);
    // mlp1 + gelu: 4000 x 3072
    gemm_tf32<1><<<dim3(MLPC/128, 32), 256>>>(y0, w_mlp1, b_mlp1, nullptr, mlp, NTOK, MLPC, CH);
    // mlp2 + residual: 4000 x 768
    gemm_tf32<2><<<dim3(CH/128, 32), 256>>>(mlp, w_mlp2, b_mlp2, y0, o, NTOK, CH, MLPC);

    final_kernel<<<(BATCH*CH*TLEN*16 + 255)/256, 256>>>(x, o, y);
}

// round 2
// speedup vs baseline: 1.2442x; 1.2442x over previous
#include <cuda_runtime.h>
#include <cuda_bf16.h>
#include <cstdint>

// ---------------------------------------------------------------------------
// Problem constants
// ---------------------------------------------------------------------------
#define BATCH 4
#define CH    768
#define TLEN  1000
#define HEADS 12
#define HDIM  64
#define WSZ   16
#define NWIN  63
#define NTOK  (BATCH*TLEN)       // 4000
#define MLPC  (4*CH)             // 3072

// ---------------------------------------------------------------------------
// Scratch (device globals; allocation-free)
// ---------------------------------------------------------------------------
__device__ float          g_s   [NTOK*CH];
__device__ __nv_bfloat16  g_snh [NTOK*CH];
__device__ float          g_qkv [NTOK*3*CH];
__device__ __nv_bfloat16  g_atth[NTOK*CH];
__device__ float          g_y0  [NTOK*CH];
__device__ __nv_bfloat16  g_y0h [NTOK*CH];
__device__ __nv_bfloat16  g_mlph[NTOK*MLPC];
__device__ float          g_o   [NTOK*CH];
__device__ __nv_bfloat16  g_wqkvT [3*CH*CH];
__device__ __nv_bfloat16  g_wprojT[CH*CH];
__device__ __nv_bfloat16  g_wmlp1T[MLPC*CH];
__device__ __nv_bfloat16  g_wmlp2T[CH*MLPC];

// ---------------------------------------------------------------------------
// Helpers
// ---------------------------------------------------------------------------
__device__ __forceinline__ void mma_bf16(float* c, const uint32_t* a, const uint32_t* b) {
    asm volatile(
        "mma.sync.aligned.m16n8k16.row.col.f32.bf16.bf16.f32 "
        "{%0,%1,%2,%3},{%4,%5,%6,%7},{%8,%9},{%0,%1,%2,%3};"
        : "+f"(c[0]), "+f"(c[1]), "+f"(c[2]), "+f"(c[3])
        : "r"(a[0]), "r"(a[1]), "r"(a[2]), "r"(a[3]), "r"(b[0]), "r"(b[1]));
}

__device__ __forceinline__ void cp_async16(void* smem_dst, const void* gsrc, int src_bytes) {
    uint32_t d = (uint32_t)__cvta_generic_to_shared(smem_dst);
    asm volatile("cp.async.cg.shared.global [%0], [%1], 16, %2;"
                 :: "r"(d), "l"(gsrc), "r"(src_bytes));
}

// ---------------------------------------------------------------------------
// K1: spatial mean.  x (B,C,T,8,8) -> s[(b*T+t)*C + c]
// ---------------------------------------------------------------------------
__global__ void spatial_mean_kernel(const float* __restrict__ x, float* __restrict__ s) {
    unsigned idx = blockIdx.x * 256u + threadIdx.x;
    unsigned row = idx >> 4;
    unsigned l16 = idx & 15u;
    if (row >= (unsigned)(BATCH*CH*TLEN)) return;
    float4 v = reinterpret_cast<const float4*>(x)[row * 16u + l16];
    float sum = v.x + v.y + v.z + v.w;
    sum += __shfl_xor_sync(0xffffffffu, sum, 1);
    sum += __shfl_xor_sync(0xffffffffu, sum, 2);
    sum += __shfl_xor_sync(0xffffffffu, sum, 4);
    sum += __shfl_xor_sync(0xffffffffu, sum, 8);
    if (l16 == 0) {
        unsigned t  = row % TLEN;
        unsigned bc = row / TLEN;
        unsigned c  = bc % CH;
        unsigned b  = bc / CH;
        s[(b*TLEN + t)*CH + c] = sum * (1.0f/64.0f);
    }
}

// ---------------------------------------------------------------------------
// K2: LayerNorm over C=768 per token -> bf16 output
// ---------------------------------------------------------------------------
__global__ void ln_kernel(const float* __restrict__ s, const float* __restrict__ gg,
                          const float* __restrict__ bb, __nv_bfloat16* __restrict__ sn) {
    __shared__ float red[2][8];
    int tok = blockIdx.x;
    int tid = threadIdx.x;                 // 256
    const float* row = s + (size_t)tok * CH;
    float v0 = row[tid], v1 = row[tid+256], v2 = row[tid+512];
    float sum = v0+v1+v2;
    float sq  = v0*v0 + v1*v1 + v2*v2;
    #pragma unroll
    for (int m = 16; m; m >>= 1) {
        sum += __shfl_xor_sync(0xffffffffu, sum, m);
        sq  += __shfl_xor_sync(0xffffffffu, sq,  m);
    }
    if ((tid & 31) == 0) { red[0][tid>>5] = sum; red[1][tid>>5] = sq; }
    __syncthreads();
    if (tid < 32) {
        float a  = (tid < 8) ? red[0][tid] : 0.f;
        float b2 = (tid < 8) ? red[1][tid] : 0.f;
        #pragma unroll
        for (int m = 4; m; m >>= 1) {
            a  += __shfl_xor_sync(0xffffffffu, a,  m);
            b2 += __shfl_xor_sync(0xffffffffu, b2, m);
        }
        if (tid == 0) { red[0][0] = a; red[1][0] = b2; }
    }
    __syncthreads();
    float mean = red[0][0] * (1.0f/768.0f);
    float var  = red[1][0] * (1.0f/768.0f) - mean*mean;
    float rstd = rsqrtf(var + 1e-5f);
    __nv_bfloat16* orow = sn + (size_t)tok * CH;
    orow[tid    ] = __float2bfloat16((v0-mean)*rstd*gg[tid    ] + bb[tid    ]);
    orow[tid+256] = __float2bfloat16((v1-mean)*rstd*gg[tid+256] + bb[tid+256]);
    orow[tid+512] = __float2bfloat16((v2-mean)*rstd*gg[tid+512] + bb[tid+512]);
}

// ---------------------------------------------------------------------------
// K3: weight convert + transpose.  W fp32 [K][N] -> WT bf16 [N][K]
// ---------------------------------------------------------------------------
__global__ void wconv_kernel(const float* __restrict__ W, __nv_bfloat16* __restrict__ WT,
                             int K, int N) {
    __shared__ float t[32][33];
    int bx = blockIdx.x * 32;   // n base
    int by = blockIdx.y * 32;   // k base
    int tx = threadIdx.x, ty = threadIdx.y;    // 32 x 8
    #pragma unroll
    for (int i = ty; i < 32; i += 8)
        t[i][tx] = W[(size_t)(by + i) * N + bx + tx];
    __syncthreads();
    #pragma unroll
    for (int i = ty; i < 32; i += 8)
        WT[(size_t)(bx + i) * K + by + tx] = __float2bfloat16(t[tx][i]);
}

// ---------------------------------------------------------------------------
// GEMM: C = A(MxK,bf16 row-major) @ BT(NxK,bf16 K-major)^T + bias
// bf16 mma.sync m16n8k16, block 128x128x32, 8 warps (2x4), warp tile 64x32,
// cp.async double buffered.
// EPI: 0 = bias -> fp32 C
//      1 = bias + exact GELU -> bf16 Ch
//      2 = bias + residual(fp32 Res) -> fp32 C
//      3 = bias -> fp32 C and bf16 Ch
// ---------------------------------------------------------------------------
template<int EPI>
__global__ __launch_bounds__(256, 2)
void gemm_bf16(const __nv_bfloat16* __restrict__ A, const __nv_bfloat16* __restrict__ BT,
               const float* __restrict__ bias, const float* __restrict__ Res,
               float* __restrict__ C, __nv_bfloat16* __restrict__ Ch,
               int M, int N, int K)
{
    __shared__ __nv_bfloat16 As[2][128][40];
    __shared__ __nv_bfloat16 Bs[2][128][40];

    int tid  = threadIdx.x;
    int lane = tid & 31, warp = tid >> 5;
    int wm = warp >> 2, wn = warp & 3;        // 2 x 4 warps
    int bm = blockIdx.y * 128, bn = blockIdx.x * 128;
    int g  = lane >> 2, tg = lane & 3;

    // copy assignment: thread -> (row, 16-half offset)
    int crow = tid >> 1;
    int coff = (tid & 1) * 16;
    int arow = bm + crow; if (arow > M-1) arow = M-1;
    int aok  = (bm + crow < M) ? 16 : 0;
    const __nv_bfloat16* gA = A  + (size_t)arow      * K + coff;
    const __nv_bfloat16* gB = BT + (size_t)(bn+crow) * K + coff;

    float acc[4][4][4];
    #pragma unroll
    for (int i = 0; i < 4; i++)
        #pragma unroll
        for (int j = 0; j < 4; j++)
            #pragma unroll
            for (int r = 0; r < 4; r++) acc[i][j][r] = 0.f;

    const int KT = K >> 5;

    // prefetch stage 0
    {
        cp_async16(&As[0][crow][coff],   gA,     aok);
        cp_async16(&As[0][crow][coff+8], gA + 8, aok);
        cp_async16(&Bs[0][crow][coff],   gB,     16);
        cp_async16(&Bs[0][crow][coff+8], gB + 8, 16);
        asm volatile("cp.async.commit_group;");
    }

    for (int kt = 0; kt < KT; kt++) {
        if (kt + 1 < KT) {
            int s  = (kt + 1) & 1;
            int k0 = (kt + 1) << 5;
            cp_async16(&As[s][crow][coff],   gA + k0,     aok);
            cp_async16(&As[s][crow][coff+8], gA + k0 + 8, aok);
            cp_async16(&Bs[s][crow][coff],   gB + k0,     16);
            cp_async16(&Bs[s][crow][coff+8], gB + k0 + 8, 16);
            asm volatile("cp.async.commit_group;");
            asm volatile("cp.async.wait_group 1;");
        } else {
            asm volatile("cp.async.wait_group 0;");
        }
        __syncthreads();

        int s = kt & 1;
        #pragma unroll
        for (int kk = 0; kk < 2; kk++) {
            int kb = kk * 16 + 2 * tg;
            uint32_t af[4][4], bf[4][2];
            #pragma unroll
            for (int mi = 0; mi < 4; mi++) {
                int rb = wm*64 + mi*16 + g;
                af[mi][0] = *reinterpret_cast<const uint32_t*>(&As[s][rb  ][kb  ]);
                af[mi][1] = *reinterpret_cast<const uint32_t*>(&As[s][rb+8][kb  ]);
                af[mi][2] = *reinterpret_cast<const uint32_t*>(&As[s][rb  ][kb+8]);
                af[mi][3] = *reinterpret_cast<const uint32_t*>(&As[s][rb+8][kb+8]);
            }
            #pragma unroll
            for (int ni = 0; ni < 4; ni++) {
                int cb = wn*32 + ni*8 + g;
                bf[ni][0] = *reinterpret_cast<const uint32_t*>(&Bs[s][cb][kb  ]);
                bf[ni][1] = *reinterpret_cast<const uint32_t*>(&Bs[s][cb][kb+8]);
            }
            #pragma unroll
            for (int mi = 0; mi < 4; mi++)
                #pragma unroll
                for (int ni = 0; ni < 4; ni++)
                    mma_bf16(acc[mi][ni], af[mi], bf[ni]);
        }
        __syncthreads();
    }

    // epilogue
    #pragma unroll
    for (int mi = 0; mi < 4; mi++) {
        int r0 = bm + wm*64 + mi*16 + g;
        #pragma unroll
        for (int ni = 0; ni < 4; ni++) {
            int c0 = bn + wn*32 + ni*8 + 2*tg;
            float b0 = bias[c0], b1 = bias[c0+1];
            #pragma unroll
            for (int half = 0; half < 2; half++) {
                int r = r0 + half*8;
                if (r < M) {
                    float v0 = acc[mi][ni][half*2]   + b0;
                    float v1 = acc[mi][ni][half*2+1] + b1;
                    if (EPI == 1) { v0 = v0 * normcdff(v0); v1 = v1 * normcdff(v1); }
                    if (EPI == 2) {
                        const float2 rr = *reinterpret_cast<const float2*>(Res + (size_t)r*N + c0);
                        v0 += rr.x; v1 += rr.y;
                    }
                    if (EPI == 0 || EPI == 2 || EPI == 3)
                        *reinterpret_cast<float2*>(C + (size_t)r*N + c0) = make_float2(v0, v1);
                    if (EPI == 1 || EPI == 3) {
                        __nv_bfloat162 h = __floats2bfloat162_rn(v0, v1);
                        *reinterpret_cast<__nv_bfloat162*>(Ch + (size_t)r*N + c0) = h;
                    }
                }
            }
        }
    }
}

// ---------------------------------------------------------------------------
// K4: windowed cosine attention (fp32 in, bf16 out)
// ---------------------------------------------------------------------------
__global__ void attn_kernel(const float* __restrict__ qkv, const float* __restrict__ tau,
                            __nv_bfloat16* __restrict__ att) {
    __shared__ float qs[16][68], ks[16][68], vs[16][68];
    __shared__ float rq[16], rk[16];
    __shared__ float at[16][17];
    __shared__ float tauv;

    int n = blockIdx.x, hh = blockIdx.y, b = blockIdx.z;
    int tid = threadIdx.x;                  // 256

    {
        int r  = tid >> 4;
        int c4 = (tid & 15) << 2;
        int t  = n*WSZ + r;
        float4 q4 = make_float4(0.f,0.f,0.f,0.f), k4 = q4, v4 = q4;
        if (t < TLEN) {
            size_t base = (size_t)(b*TLEN + t) * (3*CH) + hh*HDIM + c4;
            q4 = *reinterpret_cast<const float4*>(qkv + base);
            k4 = *reinterpret_cast<const float4*>(qkv + base + CH);
            v4 = *reinterpret_cast<const float4*>(qkv + base + 2*CH);
        }
        *reinterpret_cast<float4*>(&qs[r][c4]) = q4;
        *reinterpret_cast<float4*>(&ks[r][c4]) = k4;
        *reinterpret_cast<float4*>(&vs[r][c4]) = v4;
        if (tid == 0) tauv = tau[hh] + 1e-6f;
    }
    __syncthreads();

    if (tid < 32) {
        const float* p = (tid < 16) ? &qs[tid][0] : &ks[tid-16][0];
        float ssum = 0.f;
        #pragma unroll
        for (int i = 0; i < 64; i++) ssum += p[i]*p[i];
        float inv = 1.0f / fmaxf(sqrtf(ssum), 1e-12f);
        if (tid < 16) rq[tid] = inv; else rk[tid-16] = inv;
    }
    __syncthreads();

    int w  = tid >> 4;
    int s2 = tid & 15;
    float dot = 0.f;
    #pragma unroll
    for (int i = 0; i < 64; i++) dot += qs[w][i] * ks[s2][i];
    float logit = dot * rq[w] * rk[s2] / tauv;

    float mx = logit;
    #pragma unroll
    for (int m = 8; m; m >>= 1) mx = fmaxf(mx, __shfl_xor_sync(0xffffffffu, mx, m));
    float e = expf(logit - mx);
    float ssum = e;
    #pragma unroll
    for (int m = 8; m; m >>= 1) ssum += __shfl_xor_sync(0xffffffffu, ssum, m);
    at[w][s2] = e / ssum;
    __syncthreads();

    int c0 = (tid & 15) << 2;
    float o0=0.f, o1=0.f, o2=0.f, o3=0.f;
    #pragma unroll
    for (int ss = 0; ss < 16; ss++) {
        float a = at[w][ss];
        o0 += a * vs[ss][c0+0];
        o1 += a * vs[ss][c0+1];
        o2 += a * vs[ss][c0+2];
        o3 += a * vs[ss][c0+3];
    }
    int t = n*WSZ + w;
    if (t < TLEN) {
        __nv_bfloat16* dst = att + (size_t)(b*TLEN + t)*CH + hh*HDIM + c0;
        *reinterpret_cast<__nv_bfloat162*>(dst)     = __floats2bfloat162_rn(o0, o1);
        *reinterpret_cast<__nv_bfloat162*>(dst + 2) = __floats2bfloat162_rn(o2, o3);
    }
}

// ---------------------------------------------------------------------------
// K8: y = x + o*0.5 broadcast over 64 spatial positions
// ---------------------------------------------------------------------------
__global__ void final_kernel(const float* __restrict__ x, const float* __restrict__ o,
                             float* __restrict__ y) {
    unsigned i4 = blockIdx.x * 256u + threadIdx.x;
    if (i4 >= (unsigned)(BATCH*CH*TLEN*16)) return;
    unsigned row = i4 >> 4;
    unsigned t  = row % TLEN;
    unsigned bc = row / TLEN;
    unsigned c  = bc % CH;
    unsigned b  = bc / CH;
    float val = __ldg(o + (size_t)(b*TLEN + t)*CH + c) * 0.5f;
    float4 xv = reinterpret_cast<const float4*>(x)[i4];
    xv.x += val; xv.y += val; xv.z += val; xv.w += val;
    reinterpret_cast<float4*>(y)[i4] = xv;
}

// ---------------------------------------------------------------------------
// Launch
// ---------------------------------------------------------------------------
extern "C" void kernel_launch(void* const* d_in, const int* in_sizes, int n_in,
                              void* d_out, int out_size) {
    const float* x      = (const float*)d_in[0];
    const float* ln_g   = (const float*)d_in[1];
    const float* ln_b   = (const float*)d_in[2];
    const float* tau    = (const float*)d_in[3];
    const float* w_qkv  = (const float*)d_in[4];
    const float* b_qkv  = (const float*)d_in[5];
    const float* w_proj = (const float*)d_in[6];
    const float* b_proj = (const float*)d_in[7];
    const float* w_mlp1 = (const float*)d_in[8];
    const float* b_mlp1 = (const float*)d_in[9];
    const float* w_mlp2 = (const float*)d_in[10];
    const float* b_mlp2 = (const float*)d_in[11];
    float* y = (float*)d_out;

    float *s, *qkv, *y0, *o;
    __nv_bfloat16 *snh, *atth, *y0h, *mlph, *wqkvT, *wprojT, *wmlp1T, *wmlp2T;
    cudaGetSymbolAddress((void**)&s,      g_s);
    cudaGetSymbolAddress((void**)&snh,    g_snh);
    cudaGetSymbolAddress((void**)&qkv,    g_qkv);
    cudaGetSymbolAddress((void**)&atth,   g_atth);
    cudaGetSymbolAddress((void**)&y0,     g_y0);
    cudaGetSymbolAddress((void**)&y0h,    g_y0h);
    cudaGetSymbolAddress((void**)&mlph,   g_mlph);
    cudaGetSymbolAddress((void**)&o,      g_o);
    cudaGetSymbolAddress((void**)&wqkvT,  g_wqkvT);
    cudaGetSymbolAddress((void**)&wprojT, g_wprojT);
    cudaGetSymbolAddress((void**)&wmlp1T, g_wmlp1T);
    cudaGetSymbolAddress((void**)&wmlp2T, g_wmlp2T);

    const int elem_rows = BATCH*CH*TLEN;                 // 3,072,000

    // weight conversions (independent of activations)
    wconv_kernel<<<dim3(3*CH/32, CH/32),  dim3(32,8)>>>(w_qkv,  wqkvT,  CH,   3*CH);
    wconv_kernel<<<dim3(CH/32,   CH/32),  dim3(32,8)>>>(w_proj, wprojT, CH,   CH);
    wconv_kernel<<<dim3(MLPC/32, CH/32),  dim3(32,8)>>>(w_mlp1, wmlp1T, CH,   MLPC);
    wconv_kernel<<<dim3(CH/32,   MLPC/32),dim3(32,8)>>>(w_mlp2, wmlp2T, MLPC, CH);

    spatial_mean_kernel<<<(elem_rows*16 + 255)/256, 256>>>(x, s);
    ln_kernel<<<NTOK, 256>>>(s, ln_g, ln_b, snh);

    // qkv: 4000 x 2304
    gemm_bf16<0><<<dim3(3*CH/128, 32), 256>>>(snh, wqkvT, b_qkv, nullptr, qkv, nullptr,
                                              NTOK, 3*CH, CH);
    attn_kernel<<<dim3(NWIN, HEADS, BATCH), 256>>>(qkv, tau, atth);

    // proj: 4000 x 768 -> fp32 y0 + bf16 y0h
    gemm_bf16<3><<<dim3(CH/128, 32), 256>>>(atth, wprojT, b_proj, nullptr, y0, y0h,
                                            NTOK, CH, CH);
    // mlp1 + gelu: 4000 x 3072 -> bf16
    gemm_bf16<1><<<dim3(MLPC/128, 32), 256>>>(y0h, wmlp1T, b_mlp1, nullptr, nullptr, mlph,
                                              NTOK, MLPC, CH);
    // mlp2 + residual: 4000 x 768 -> fp32
    gemm_bf16<2><<<dim3(CH/128, 32), 256>>>(mlph, wmlp2T, b_mlp2, y0, o, nullptr,
                                            NTOK, CH, MLPC);

    final_kernel<<<(BATCH*CH*TLEN*16 + 255)/256, 256>>>(x, o, y);
}

// round 8
// speedup vs baseline: 1.2674x; 1.0186x over previous
#include <cuda_runtime.h>
#include <cuda_bf16.h>
#include <cstdint>

// ---------------------------------------------------------------------------
// Problem constants
// ---------------------------------------------------------------------------
#define BATCH 4
#define CH    768
#define TLEN  1000
#define HEADS 12
#define HDIM  64
#define WSZ   16
#define NWIN  63
#define NTOK  (BATCH*TLEN)       // 4000
#define MLPC  (4*CH)             // 3072

// ---------------------------------------------------------------------------
// Scratch (device globals; allocation-free)
// ---------------------------------------------------------------------------
__device__ float          g_s   [NTOK*CH];
__device__ __nv_bfloat16  g_snh [NTOK*CH];
__device__ float          g_qkv [NTOK*3*CH];
__device__ __nv_bfloat16  g_atth[NTOK*CH];
__device__ float          g_y0  [NTOK*CH];
__device__ __nv_bfloat16  g_y0h [NTOK*CH];
__device__ __nv_bfloat16  g_mlph[NTOK*MLPC];
__device__ float          g_o   [NTOK*CH];
__device__ __nv_bfloat16  g_wqkvT [3*CH*CH];
__device__ __nv_bfloat16  g_wprojT[CH*CH];
__device__ __nv_bfloat16  g_wmlp1T[MLPC*CH];
__device__ __nv_bfloat16  g_wmlp2T[CH*MLPC];

// ---------------------------------------------------------------------------
// Helpers
// ---------------------------------------------------------------------------
__device__ __forceinline__ uint32_t smem_u32(const void* p) {
    uint32_t a;
    asm("{ .reg .u64 t; cvta.to.shared.u64 t, %1; cvt.u32.u64 %0, t; }" : "=r"(a) : "l"(p));
    return a;
}

__device__ __forceinline__ void mma_bf16(float* c, const uint32_t* a, const uint32_t* b) {
    asm volatile(
        "mma.sync.aligned.m16n8k16.row.col.f32.bf16.bf16.f32 "
        "{%0,%1,%2,%3},{%4,%5,%6,%7},{%8,%9},{%0,%1,%2,%3};"
        : "+f"(c[0]), "+f"(c[1]), "+f"(c[2]), "+f"(c[3])
        : "r"(a[0]), "r"(a[1]), "r"(a[2]), "r"(a[3]), "r"(b[0]), "r"(b[1]));
}

__device__ __forceinline__ void cp_async16_sh(uint32_t dst, const void* src, int n) {
    asm volatile("cp.async.cg.shared.global [%0], [%1], 16, %2;"
                 :: "r"(dst), "l"(src), "r"(n));
}

#define LDSM_X4(r0, r1, r2, r3, addr)                                         \
    asm volatile("ldmatrix.sync.aligned.m8n8.x4.shared.b16 {%0,%1,%2,%3}, [%4];" \
                 : "=r"(r0), "=r"(r1), "=r"(r2), "=r"(r3) : "r"(addr))

// ---------------------------------------------------------------------------
// K1: spatial mean.  x (B,C,T,8,8) -> s[(b*T+t)*C + c]
// ---------------------------------------------------------------------------
__global__ void spatial_mean_kernel(const float* __restrict__ x, float* __restrict__ s) {
    unsigned idx = blockIdx.x * 256u + threadIdx.x;
    unsigned row = idx >> 4;
    unsigned l16 = idx & 15u;
    if (row >= (unsigned)(BATCH*CH*TLEN)) return;
    float4 v = reinterpret_cast<const float4*>(x)[row * 16u + l16];
    float sum = v.x + v.y + v.z + v.w;
    sum += __shfl_xor_sync(0xffffffffu, sum, 1);
    sum += __shfl_xor_sync(0xffffffffu, sum, 2);
    sum += __shfl_xor_sync(0xffffffffu, sum, 4);
    sum += __shfl_xor_sync(0xffffffffu, sum, 8);
    if (l16 == 0) {
        unsigned t  = row % TLEN;
        unsigned bc = row / TLEN;
        unsigned c  = bc % CH;
        unsigned b  = bc / CH;
        s[(b*TLEN + t)*CH + c] = sum * (1.0f/64.0f);
    }
}

// ---------------------------------------------------------------------------
// K2: LayerNorm over C=768 per token -> bf16 output
// ---------------------------------------------------------------------------
__global__ void ln_kernel(const float* __restrict__ s, const float* __restrict__ gg,
                          const float* __restrict__ bb, __nv_bfloat16* __restrict__ sn) {
    __shared__ float red[2][8];
    int tok = blockIdx.x;
    int tid = threadIdx.x;                 // 256
    const float* row = s + (size_t)tok * CH;
    float v0 = row[tid], v1 = row[tid+256], v2 = row[tid+512];
    float sum = v0+v1+v2;
    float sq  = v0*v0 + v1*v1 + v2*v2;
    #pragma unroll
    for (int m = 16; m; m >>= 1) {
        sum += __shfl_xor_sync(0xffffffffu, sum, m);
        sq  += __shfl_xor_sync(0xffffffffu, sq,  m);
    }
    if ((tid & 31) == 0) { red[0][tid>>5] = sum; red[1][tid>>5] = sq; }
    __syncthreads();
    if (tid < 32) {
        float a  = (tid < 8) ? red[0][tid] : 0.f;
        float b2 = (tid < 8) ? red[1][tid] : 0.f;
        #pragma unroll
        for (int m = 4; m; m >>= 1) {
            a  += __shfl_xor_sync(0xffffffffu, a,  m);
            b2 += __shfl_xor_sync(0xffffffffu, b2, m);
        }
        if (tid == 0) { red[0][0] = a; red[1][0] = b2; }
    }
    __syncthreads();
    float mean = red[0][0] * (1.0f/768.0f);
    float var  = red[1][0] * (1.0f/768.0f) - mean*mean;
    float rstd = rsqrtf(var + 1e-5f);
    __nv_bfloat16* orow = sn + (size_t)tok * CH;
    orow[tid    ] = __float2bfloat16((v0-mean)*rstd*gg[tid    ] + bb[tid    ]);
    orow[tid+256] = __float2bfloat16((v1-mean)*rstd*gg[tid+256] + bb[tid+256]);
    orow[tid+512] = __float2bfloat16((v2-mean)*rstd*gg[tid+512] + bb[tid+512]);
}

// ---------------------------------------------------------------------------
// K3: weight convert + transpose.  W fp32 [K][N] -> WT bf16 [N][K]
// ---------------------------------------------------------------------------
__global__ void wconv_kernel(const float* __restrict__ W, __nv_bfloat16* __restrict__ WT,
                             int K, int N) {
    __shared__ float t[32][33];
    int bx = blockIdx.x * 32;   // n base
    int by = blockIdx.y * 32;   // k base
    int tx = threadIdx.x, ty = threadIdx.y;    // 32 x 8
    #pragma unroll
    for (int i = ty; i < 32; i += 8)
        t[i][tx] = W[(size_t)(by + i) * N + bx + tx];
    __syncthreads();
    #pragma unroll
    for (int i = ty; i < 32; i += 8)
        WT[(size_t)(bx + i) * K + by + tx] = __float2bfloat16(t[tx][i]);
}

// ---------------------------------------------------------------------------
// GEMM: C = A(MxK,bf16 row-major) @ BT(NxK,bf16 K-major)^T + bias
// bf16 mma.sync m16n8k16, block 128x128x32, 8 warps (2x4), warp tile 64x32.
// 3-stage cp.async pipeline, ldmatrix.x4 fragment loads (conflict-free,
// 40-half row stride).
// EPI: 0 = bias -> fp32 C
//      1 = bias + exact GELU -> bf16 Ch
//      2 = bias + residual(fp32 Res) -> fp32 C
//      3 = bias -> fp32 C and bf16 Ch
// ---------------------------------------------------------------------------
#define GS_STAGE  10240u           // 128 rows * 40 halfs * 2B, per operand per stage
#define GS_BOFF   30720u           // 3 stages of A
#define GS_TOTAL  61440            // 3 * (A + B)

template<int EPI>
__global__ __launch_bounds__(256, 2)
void gemm_bf16(const __nv_bfloat16* __restrict__ A, const __nv_bfloat16* __restrict__ BT,
               const float* __restrict__ bias, const float* __restrict__ Res,
               float* __restrict__ C, __nv_bfloat16* __restrict__ Ch,
               int M, int N, int K)
{
    extern __shared__ __nv_bfloat16 smem[];
    const uint32_t smemu = smem_u32(smem);

    int tid  = threadIdx.x;
    int lane = tid & 31, warp = tid >> 5;
    int wm = warp >> 2, wn = warp & 3;        // 2 x 4 warps
    int bm = blockIdx.y * 128, bn = blockIdx.x * 128;
    int g  = lane >> 2, tg = lane & 3;

    // ---- copy assignment: thread -> (row, 16-half offset) ----
    int crow = tid >> 1;
    int coffh = (tid & 1) * 16;
    int arow = bm + crow; if (arow > M-1) arow = M-1;
    int aok  = (bm + crow < M) ? 16 : 0;
    const __nv_bfloat16* gA = A  + (size_t)arow      * K + coffh;
    const __nv_bfloat16* gB = BT + (size_t)(bn+crow) * K + coffh;
    const uint32_t dstOff = (uint32_t)crow * 80u + (uint32_t)coffh * 2u;

    // ---- ldmatrix lane addressing (bytes within a stage) ----
    // A: row = wm*64 + (lane&7) + ((lane>>3)&1)*8 (+ mi*16), col = (lane>>4)*8 (+ kb)
    const uint32_t aFrag = (uint32_t)(wm*64 + (lane & 7) + ((lane >> 3) & 1) * 8) * 80u
                         + (uint32_t)((lane >> 4) * 8) * 2u;
    // B: row = wn*32 + (lane&7) + ((lane>>4)&1)*8 (+ p*16), col = ((lane>>3)&1)*8 (+ kb)
    const uint32_t bFrag = (uint32_t)(wn*32 + (lane & 7) + ((lane >> 4) & 1) * 8) * 80u
                         + (uint32_t)(((lane >> 3) & 1) * 8) * 2u;

    float acc[4][4][4];
    #pragma unroll
    for (int i = 0; i < 4; i++)
        #pragma unroll
        for (int j = 0; j < 4; j++)
            #pragma unroll
            for (int r = 0; r < 4; r++) acc[i][j][r] = 0.f;

    const int KT = K >> 5;

    // ---- pipeline prefetch ----
    auto prefetch = [&](int c) {
        int st = c % 3;
        uint32_t da = smemu + (uint32_t)st * GS_STAGE + dstOff;
        uint32_t db = da + GS_BOFF;
        const __nv_bfloat16* sa = gA + c * 32;
        const __nv_bfloat16* sb = gB + c * 32;
        cp_async16_sh(da,      sa,     aok);
        cp_async16_sh(da + 16, sa + 8, aok);
        cp_async16_sh(db,      sb,     16);
        cp_async16_sh(db + 16, sb + 8, 16);
        asm volatile("cp.async.commit_group;");
    };

    prefetch(0);
    if (KT > 1) prefetch(1);

    for (int kt = 0; kt < KT; kt++) {
        if (kt + 1 < KT) asm volatile("cp.async.wait_group 1;");
        else             asm volatile("cp.async.wait_group 0;");
        __syncthreads();
        if (kt + 2 < KT) prefetch(kt + 2);

        int st = kt % 3;
        uint32_t aB = smemu + (uint32_t)st * GS_STAGE + aFrag;
        uint32_t bB = aB - aFrag + GS_BOFF + bFrag;
        #pragma unroll
        for (int kk = 0; kk < 2; kk++) {
            uint32_t kby = (uint32_t)kk * 32u;
            uint32_t af[4][4], bf[4][2];
            #pragma unroll
            for (int mi = 0; mi < 4; mi++)
                LDSM_X4(af[mi][0], af[mi][1], af[mi][2], af[mi][3],
                        aB + (uint32_t)mi * (16u*80u) + kby);
            #pragma unroll
            for (int p = 0; p < 2; p++)
                LDSM_X4(bf[2*p][0], bf[2*p][1], bf[2*p+1][0], bf[2*p+1][1],
                        bB + (uint32_t)p * (16u*80u) + kby);
            #pragma unroll
            for (int mi = 0; mi < 4; mi++)
                #pragma unroll
                for (int ni = 0; ni < 4; ni++)
                    mma_bf16(acc[mi][ni], af[mi], bf[ni]);
        }
        __syncthreads();
    }

    // ---- epilogue ----
    #pragma unroll
    for (int mi = 0; mi < 4; mi++) {
        int r0 = bm + wm*64 + mi*16 + g;
        #pragma unroll
        for (int ni = 0; ni < 4; ni++) {
            int c0 = bn + wn*32 + ni*8 + 2*tg;
            float b0 = bias[c0], b1 = bias[c0+1];
            #pragma unroll
            for (int half = 0; half < 2; half++) {
                int r = r0 + half*8;
                if (r < M) {
                    float v0 = acc[mi][ni][half*2]   + b0;
                    float v1 = acc[mi][ni][half*2+1] + b1;
                    if (EPI == 1) { v0 = v0 * normcdff(v0); v1 = v1 * normcdff(v1); }
                    if (EPI == 2) {
                        const float2 rr = *reinterpret_cast<const float2*>(Res + (size_t)r*N + c0);
                        v0 += rr.x; v1 += rr.y;
                    }
                    if (EPI == 0 || EPI == 2 || EPI == 3)
                        *reinterpret_cast<float2*>(C + (size_t)r*N + c0) = make_float2(v0, v1);
                    if (EPI == 1 || EPI == 3) {
                        __nv_bfloat162 h = __floats2bfloat162_rn(v0, v1);
                        *reinterpret_cast<__nv_bfloat162*>(Ch + (size_t)r*N + c0) = h;
                    }
                }
            }
        }
    }
}

// ---------------------------------------------------------------------------
// K4: windowed cosine attention (fp32 in, bf16 out)
// ---------------------------------------------------------------------------
__global__ void attn_kernel(const float* __restrict__ qkv, const float* __restrict__ tau,
                            __nv_bfloat16* __restrict__ att) {
    __shared__ float qs[16][68], ks[16][68], vs[16][68];
    __shared__ float rq[16], rk[16];
    __shared__ float at[16][17];
    __shared__ float tauv;

    int n = blockIdx.x, hh = blockIdx.y, b = blockIdx.z;
    int tid = threadIdx.x;                  // 256

    {
        int rr  = tid >> 4;
        int c4 = (tid & 15) << 2;
        int t  = n*WSZ + rr;
        float4 q4 = make_float4(0.f,0.f,0.f,0.f), k4 = q4, v4 = q4;
        if (t < TLEN) {
            size_t bb = (size_t)(b*TLEN + t) * (3*CH) + hh*HDIM + c4;
            q4 = *reinterpret_cast<const float4*>(qkv + bb);
            k4 = *reinterpret_cast<const float4*>(qkv + bb + CH);
            v4 = *reinterpret_cast<const float4*>(qkv + bb + 2*CH);
        }
        *reinterpret_cast<float4*>(&qs[rr][c4]) = q4;
        *reinterpret_cast<float4*>(&ks[rr][c4]) = k4;
        *reinterpret_cast<float4*>(&vs[rr][c4]) = v4;
        if (tid == 0) tauv = tau[hh] + 1e-6f;
    }
    __syncthreads();

    if (tid < 32) {
        const float* p = (tid < 16) ? &qs[tid][0] : &ks[tid-16][0];
        float ssum = 0.f;
        #pragma unroll
        for (int i = 0; i < 64; i++) ssum += p[i]*p[i];
        float inv = 1.0f / fmaxf(sqrtf(ssum), 1e-12f);
        if (tid < 16) rq[tid] = inv; else rk[tid-16] = inv;
    }
    __syncthreads();

    int w  = tid >> 4;
    int s2 = tid & 15;
    float dot = 0.f;
    #pragma unroll
    for (int i = 0; i < 64; i++) dot += qs[w][i] * ks[s2][i];
    float logit = dot * rq[w] * rk[s2] / tauv;

    float mx = logit;
    #pragma unroll
    for (int m = 8; m; m >>= 1) mx = fmaxf(mx, __shfl_xor_sync(0xffffffffu, mx, m));
    float e = expf(logit - mx);
    float ssum = e;
    #pragma unroll
    for (int m = 8; m; m >>= 1) ssum += __shfl_xor_sync(0xffffffffu, ssum, m);
    at[w][s2] = e / ssum;
    __syncthreads();

    int c0 = (tid & 15) << 2;
    float o0=0.f, o1=0.f, o2=0.f, o3=0.f;
    #pragma unroll
    for (int ss = 0; ss < 16; ss++) {
        float a = at[w][ss];
        o0 += a * vs[ss][c0+0];
        o1 += a * vs[ss][c0+1];
        o2 += a * vs[ss][c0+2];
        o3 += a * vs[ss][c0+3];
    }
    int t = n*WSZ + w;
    if (t < TLEN) {
        __nv_bfloat16* dst = att + (size_t)(b*TLEN + t)*CH + hh*HDIM + c0;
        *reinterpret_cast<__nv_bfloat162*>(dst)     = __floats2bfloat162_rn(o0, o1);
        *reinterpret_cast<__nv_bfloat162*>(dst + 2) = __floats2bfloat162_rn(o2, o3);
    }
}

// ---------------------------------------------------------------------------
// K8: y = x + o*0.5 broadcast over 64 spatial positions
// ---------------------------------------------------------------------------
__global__ void final_kernel(const float* __restrict__ x, const float* __restrict__ o,
                             float* __restrict__ y) {
    unsigned i4 = blockIdx.x * 256u + threadIdx.x;
    if (i4 >= (unsigned)(BATCH*CH*TLEN*16)) return;
    unsigned row = i4 >> 4;
    unsigned t  = row % TLEN;
    unsigned bc = row / TLEN;
    unsigned c  = bc % CH;
    unsigned b  = bc / CH;
    float val = __ldg(o + (size_t)(b*TLEN + t)*CH + c) * 0.5f;
    float4 xv = reinterpret_cast<const float4*>(x)[i4];
    xv.x += val; xv.y += val; xv.z += val; xv.w += val;
    reinterpret_cast<float4*>(y)[i4] = xv;
}

// ---------------------------------------------------------------------------
// Launch
// ---------------------------------------------------------------------------
extern "C" void kernel_launch(void* const* d_in, const int* in_sizes, int n_in,
                              void* d_out, int out_size) {
    const float* x      = (const float*)d_in[0];
    const float* ln_g   = (const float*)d_in[1];
    const float* ln_b   = (const float*)d_in[2];
    const float* tau    = (const float*)d_in[3];
    const float* w_qkv  = (const float*)d_in[4];
    const float* b_qkv  = (const float*)d_in[5];
    const float* w_proj = (const float*)d_in[6];
    const float* b_proj = (const float*)d_in[7];
    const float* w_mlp1 = (const float*)d_in[8];
    const float* b_mlp1 = (const float*)d_in[9];
    const float* w_mlp2 = (const float*)d_in[10];
    const float* b_mlp2 = (const float*)d_in[11];
    float* y = (float*)d_out;

    float *s, *qkv, *y0, *o;
    __nv_bfloat16 *snh, *atth, *y0h, *mlph, *wqkvT, *wprojT, *wmlp1T, *wmlp2T;
    cudaGetSymbolAddress((void**)&s,      g_s);
    cudaGetSymbolAddress((void**)&snh,    g_snh);
    cudaGetSymbolAddress((void**)&qkv,    g_qkv);
    cudaGetSymbolAddress((void**)&atth,   g_atth);
    cudaGetSymbolAddress((void**)&y0,     g_y0);
    cudaGetSymbolAddress((void**)&y0h,    g_y0h);
    cudaGetSymbolAddress((void**)&mlph,   g_mlph);
    cudaGetSymbolAddress((void**)&o,      g_o);
    cudaGetSymbolAddress((void**)&wqkvT,  g_wqkvT);
    cudaGetSymbolAddress((void**)&wprojT, g_wprojT);
    cudaGetSymbolAddress((void**)&wmlp1T, g_wmlp1T);
    cudaGetSymbolAddress((void**)&wmlp2T, g_wmlp2T);

    cudaFuncSetAttribute(gemm_bf16<0>, cudaFuncAttributeMaxDynamicSharedMemorySize, GS_TOTAL);
    cudaFuncSetAttribute(gemm_bf16<1>, cudaFuncAttributeMaxDynamicSharedMemorySize, GS_TOTAL);
    cudaFuncSetAttribute(gemm_bf16<2>, cudaFuncAttributeMaxDynamicSharedMemorySize, GS_TOTAL);
    cudaFuncSetAttribute(gemm_bf16<3>, cudaFuncAttributeMaxDynamicSharedMemorySize, GS_TOTAL);

    const int elem_rows = BATCH*CH*TLEN;                 // 3,072,000

    // weight conversions (independent of activations)
    wconv_kernel<<<dim3(3*CH/32, CH/32),  dim3(32,8)>>>(w_qkv,  wqkvT,  CH,   3*CH);
    wconv_kernel<<<dim3(CH/32,   CH/32),  dim3(32,8)>>>(w_proj, wprojT, CH,   CH);
    wconv_kernel<<<dim3(MLPC/32, CH/32),  dim3(32,8)>>>(w_mlp1, wmlp1T, CH,   MLPC);
    wconv_kernel<<<dim3(CH/32,   MLPC/32),dim3(32,8)>>>(w_mlp2, wmlp2T, MLPC, CH);

    spatial_mean_kernel<<<(elem_rows*16 + 255)/256, 256>>>(x, s);
    ln_kernel<<<NTOK, 256>>>(s, ln_g, ln_b, snh);

    // qkv: 4000 x 2304
    gemm_bf16<0><<<dim3(3*CH/128, 32), 256, GS_TOTAL>>>(snh, wqkvT, b_qkv, nullptr,
                                                        qkv, nullptr, NTOK, 3*CH, CH);
    attn_kernel<<<dim3(NWIN, HEADS, BATCH), 256>>>(qkv, tau, atth);

    // proj: 4000 x 768 -> fp32 y0 + bf16 y0h
    gemm_bf16<3><<<dim3(CH/128, 32), 256, GS_TOTAL>>>(atth, wprojT, b_proj, nullptr,
                                                      y0, y0h, NTOK, CH, CH);
    // mlp1 + gelu: 4000 x 3072 -> bf16
    gemm_bf16<1><<<dim3(MLPC/128, 32), 256, GS_TOTAL>>>(y0h, wmlp1T, b_mlp1, nullptr,
                                                        nullptr, mlph, NTOK, MLPC, CH);
    // mlp2 + residual: 4000 x 768 -> fp32
    gemm_bf16<2><<<dim3(CH/128, 32), 256, GS_TOTAL>>>(mlph, wmlp2T, b_mlp2, y0,
                                                      o, nullptr, NTOK, CH, MLPC);

    final_kernel<<<(BATCH*CH*TLEN*16 + 255)/256, 256>>>(x, o, y);
}